// round 5
// baseline (speedup 1.0000x reference)
#include <cuda_runtime.h>

#define N_ 64
#define C_ 64
#define T_ 300
#define V_ 25
#define F_ 64
#define TPB 4                   // t's per CTA; 300 % 4 == 0
#define MR 100                  // real rows = TPB * V_
#define MP 128                  // padded rows = TPB * 32
#define HS_STRIDE 68            // multiple of 4 -> float4-aligned for every row
#define ATT_STRIDE 28
#define OS_STRIDE 67            // scalar stores only
#define XS_STRIDE 128
#define ALPHA 0.2f
#define NEG_INF_ -9.0e15f

// shared layout (float offsets)
#define OFF_WS   0
#define OFF_HS   (OFF_WS + C_ * F_)                 // 4096
#define OFF_ATT  (OFF_HS + MP * HS_STRIDE)          // 12800
#define OFF_XS   (OFF_ATT + MP * ATT_STRIDE)        // 16384 (xsT; reused as out staging)
#define OFF_F1   (OFF_XS + C_ * XS_STRIDE)          // 24576
#define OFF_F2   (OFF_F1 + MP)
#define OFF_A1   (OFF_F2 + MP)
#define OFF_A2   (OFF_A1 + F_)
#define OFF_ADJ  (OFF_A2 + F_)
#define SMEM_FLOATS (OFF_ADJ + V_ * V_)
#define SMEM_BYTES  (SMEM_FLOATS * 4)               // ~102.4 KB -> 2 CTAs/SM

__global__ void __launch_bounds__(512, 2) gat_kernel(
    const float* __restrict__ x,    // (N, C, T, V)
    const int*   __restrict__ adj,  // (V, V)
    const float* __restrict__ W,    // (C, F)
    const float* __restrict__ a,    // (2F, 1)
    float*       __restrict__ out)  // (N, F, T, V)
{
    extern __shared__ float sm[];
    float* Ws   = sm + OFF_WS;
    float* hs   = sm + OFF_HS;
    float* attm = sm + OFF_ATT;
    float* xsT  = sm + OFF_XS;
    float* f1s  = sm + OFF_F1;
    float* f2s  = sm + OFF_F2;
    float* a1s  = sm + OFF_A1;
    float* a2s  = sm + OFF_A2;
    int*   adjs = (int*)(sm + OFF_ADJ);

    const int tid = threadIdx.x;
    const int tf  = tid & 15;         // 0..15 -> f0 = 4*tf
    const int tm  = tid >> 4;         // 0..31 -> r0 = 4*tm (padded row)
    const int f0  = tf << 2;
    const int r0  = tm << 2;

    // ---- stage constants + zero att ----
    for (int i = tid; i < C_ * F_; i += 512) Ws[i] = W[i];
    if (tid < F_) { a1s[tid] = a[tid]; a2s[tid] = a[F_ + tid]; }
    for (int i = tid; i < V_ * V_; i += 512) adjs[i] = adj[i];
    for (int i = tid; i < MP * ATT_STRIDE; i += 512) attm[i] = 0.f;

    const int n  = blockIdx.x / (T_ / TPB);
    const int bt = blockIdx.x % (T_ / TPB);
    const int t0 = bt * TPB;
    const float* xn   = x   + (size_t)n * C_ * T_ * V_ + (size_t)t0 * V_;
    float*       outn = out + (size_t)n * F_ * T_ * V_ + (size_t)t0 * V_;

    // ---- load x into padded transposed layout: xsT[c][32g+v] ; dead rows = 0 ----
    for (int i = tid; i < C_ * MP; i += 512) {
        const int c = i >> 7;
        const int r = i & 127;
        const int g = r >> 5;
        const int v = r & 31;
        xsT[c * XS_STRIDE + r] = (v < V_) ? xn[c * (T_ * V_) + g * V_ + v] : 0.f;
    }
    __syncthreads();

    const float4 a1v = *(const float4*)&a1s[f0];
    const float4 a2v = *(const float4*)&a2s[f0];

    // ---- GEMM1: hs[r][f] = sum_c xsT[c][r] * Ws[c][f]; tile 4r x 4f ----
    float acc[4][4];
    #pragma unroll
    for (int k = 0; k < 4; ++k)
        #pragma unroll
        for (int ff = 0; ff < 4; ++ff) acc[k][ff] = 0.f;

    #pragma unroll 16
    for (int c = 0; c < C_; ++c) {
        const float4 wv = *(const float4*)&Ws[c * F_ + f0];
        const float4 xv = *(const float4*)&xsT[c * XS_STRIDE + r0];
        const float xm[4] = {xv.x, xv.y, xv.z, xv.w};
        #pragma unroll
        for (int k = 0; k < 4; ++k) {
            acc[k][0] += xm[k] * wv.x;
            acc[k][1] += xm[k] * wv.y;
            acc[k][2] += xm[k] * wv.z;
            acc[k][3] += xm[k] * wv.w;
        }
    }

    float s1[4], s2[4];
    #pragma unroll
    for (int k = 0; k < 4; ++k) {
        *(float4*)&hs[(r0 + k) * HS_STRIDE + f0] =
            make_float4(acc[k][0], acc[k][1], acc[k][2], acc[k][3]);
        s1[k] = acc[k][0] * a1v.x + acc[k][1] * a1v.y + acc[k][2] * a1v.z + acc[k][3] * a1v.w;
        s2[k] = acc[k][0] * a2v.x + acc[k][1] * a2v.y + acc[k][2] * a2v.z + acc[k][3] * a2v.w;
    }
    #pragma unroll
    for (int d = 1; d < 16; d <<= 1) {
        #pragma unroll
        for (int k = 0; k < 4; ++k) {
            s1[k] += __shfl_xor_sync(0xffffffffu, s1[k], d);
            s2[k] += __shfl_xor_sync(0xffffffffu, s2[k], d);
        }
    }
    if (tf == 0) {
        #pragma unroll
        for (int k = 0; k < 4; ++k) { f1s[r0 + k] = s1[k]; f2s[r0 + k] = s2[k]; }
    }
    __syncthreads();

    // ---- masked leaky-relu + row softmax (one thread per padded row) ----
    if (tid < MP) {
        const int r = tid;
        const int v = r & 31;
        if (v < V_) {
            const int base = r & ~31;   // group base (padded)
            const float fi = f1s[r];
            float e[V_];
            float mx = NEG_INF_;
            #pragma unroll
            for (int j = 0; j < V_; ++j) {
                float val = fi + f2s[base + j];
                val = (val > 0.f) ? val : ALPHA * val;
                val = (adjs[v * V_ + j] > 0) ? val : NEG_INF_;
                e[j] = val;
                mx = fmaxf(mx, val);
            }
            float s = 0.f;
            #pragma unroll
            for (int j = 0; j < V_; ++j) { const float p = __expf(e[j] - mx); e[j] = p; s += p; }
            const float inv = 1.f / s;
            #pragma unroll
            for (int j = 0; j < V_; ++j) attm[r * ATT_STRIDE + j] = e[j] * inv;
        }
    }
    __syncthreads();

    // ---- GEMM2: o[r][f] = sum_j attm[r][j] * hs[base + j][f]; no selects ----
    const int base = r0 & ~31;
    float o[4][4];
    #pragma unroll
    for (int k = 0; k < 4; ++k)
        #pragma unroll
        for (int ff = 0; ff < 4; ++ff) o[k][ff] = 0.f;

    #pragma unroll
    for (int jb = 0; jb < ATT_STRIDE; jb += 4) {
        float4 h0 = *(const float4*)&hs[(base + jb + 0) * HS_STRIDE + f0];
        float4 h1 = *(const float4*)&hs[(base + jb + 1) * HS_STRIDE + f0];
        float4 h2 = *(const float4*)&hs[(base + jb + 2) * HS_STRIDE + f0];
        float4 h3 = *(const float4*)&hs[(base + jb + 3) * HS_STRIDE + f0];
        #pragma unroll
        for (int k = 0; k < 4; ++k) {
            const float4 av = *(const float4*)&attm[(r0 + k) * ATT_STRIDE + jb];
            o[k][0] += av.x * h0.x + av.y * h1.x + av.z * h2.x + av.w * h3.x;
            o[k][1] += av.x * h0.y + av.y * h1.y + av.z * h2.y + av.w * h3.y;
            o[k][2] += av.x * h0.z + av.y * h1.z + av.z * h2.z + av.w * h3.z;
            o[k][3] += av.x * h0.w + av.y * h1.w + av.z * h2.w + av.w * h3.w;
        }
    }

    // ---- ELU + stage transposed into xsT region (stride 67, scalar stores) ----
    float* os = xsT;
    __syncthreads();   // everyone done reading xsT/hs before reuse/overwrite
    #pragma unroll
    for (int k = 0; k < 4; ++k) {
        const int r = r0 + k;
        const int v = r & 31;
        if (v < V_) {
            const int m = (r >> 5) * V_ + v;   // real row
            #pragma unroll
            for (int ff = 0; ff < 4; ++ff) {
                float val = o[k][ff];
                val = (val > 0.f) ? val : expm1f(val);
                os[m * OS_STRIDE + f0 + ff] = val;
            }
        }
    }
    __syncthreads();

    // ---- store: out[n][f][t0*25 + m], MR contiguous floats per f ----
    for (int idx = tid; idx < F_ * MR; idx += 512) {
        const int f = idx / MR;
        const int m = idx - f * MR;
        outn[f * (T_ * V_) + m] = os[m * OS_STRIDE + f];
    }
}

extern "C" void kernel_launch(void* const* d_in, const int* in_sizes, int n_in,
                              void* d_out, int out_size)
{
    const float* x   = (const float*)d_in[0];
    const int*   adj = (const int*)  d_in[1];
    const float* W   = (const float*)d_in[2];
    const float* a   = (const float*)d_in[3];
    float* out = (float*)d_out;

    cudaFuncSetAttribute(gat_kernel, cudaFuncAttributeMaxDynamicSharedMemorySize, SMEM_BYTES);
    dim3 grid(N_ * (T_ / TPB));
    gat_kernel<<<grid, 512, SMEM_BYTES>>>(x, adj, W, a, out);
}

// round 6
// speedup vs baseline: 1.1834x; 1.1834x over previous
#include <cuda_runtime.h>

#define N_ 64
#define C_ 64
#define T_ 300
#define V_ 25
#define F_ 64
#define TPB 5
#define M_ 125                 // TPB * V_
#define MP 128                 // padded M
#define HS_STRIDE 68
#define ATT_STRIDE 28
#define OS_STRIDE 67
#define XS_STRIDE 128
#define ALPHA 0.2f
#define NEG_INF_ -9.0e15f

// shared memory layout (float offsets)
#define OFF_WS   0
#define OFF_HS   (OFF_WS + C_ * F_)              // 4096
#define OFF_ATT  (OFF_HS + MP * HS_STRIDE)       // 12800
#define OFF_XS   (OFF_ATT + MP * ATT_STRIDE)     // 16384  (xsT / out staging union)
#define XS_SIZE  8704
#define OFF_F1   (OFF_XS + XS_SIZE)              // 25088
#define OFF_F2   (OFF_F1 + MP)
#define OFF_A1   (OFF_F2 + MP)
#define OFF_A2   (OFF_A1 + F_)
#define OFF_ADJ  (OFF_A2 + F_)
#define SMEM_FLOATS (OFF_ADJ + V_ * V_)
#define SMEM_BYTES  (SMEM_FLOATS * 4)            // ~104.4 KB -> 2 CTAs/SM

typedef unsigned long long u64;
#define FMA2(d, a, b, c) asm("fma.rn.f32x2 %0, %1, %2, %3;" : "=l"(d) : "l"(a), "l"(b), "l"(c))
#define PACK2(d, lo, hi) asm("mov.b64 %0, {%1, %2};" : "=l"(d) : "f"(lo), "f"(hi))
#define UNPACK2(lo, hi, s) asm("mov.b64 {%0, %1}, %2;" : "=f"(lo), "=f"(hi) : "l"(s))

__global__ void __launch_bounds__(256, 2) gat_kernel(
    const float* __restrict__ x,    // (N, C, T, V)
    const int*   __restrict__ adj,  // (V, V)
    const float* __restrict__ W,    // (C, F)
    const float* __restrict__ a,    // (2F, 1)
    float*       __restrict__ out)  // (N, F, T, V)
{
    extern __shared__ float sm[];
    float* Ws   = sm + OFF_WS;
    float* hs   = sm + OFF_HS;
    float* attm = sm + OFF_ATT;
    float* xsT  = sm + OFF_XS;
    float* f1s  = sm + OFF_F1;
    float* f2s  = sm + OFF_F2;
    float* a1s  = sm + OFF_A1;
    float* a2s  = sm + OFF_A2;
    int*   adjs = (int*)(sm + OFF_ADJ);

    const int tid = threadIdx.x;
    const int tf  = tid & 15;        // f0 = 4*tf
    const int tm  = tid >> 4;        // m0 = 8*tm
    const int f0  = tf << 2;
    const int m0  = tm << 3;

    // ---- stage constants ----
    for (int i = tid; i < C_ * F_; i += 256) Ws[i] = W[i];
    if (tid < F_) { a1s[tid] = a[tid]; a2s[tid] = a[F_ + tid]; }
    for (int i = tid; i < V_ * V_; i += 256) adjs[i] = adj[i];
    for (int i = tid; i < MP * ATT_STRIDE; i += 256) attm[i] = 0.f;

    const int n  = blockIdx.x / (T_ / TPB);
    const int bt = blockIdx.x % (T_ / TPB);
    const int t0 = bt * TPB;
    const float* xn   = x   + (size_t)n * C_ * T_ * V_ + (size_t)t0 * V_;
    float*       outn = out + (size_t)n * F_ * T_ * V_ + (size_t)t0 * V_;

    // ---- load x: xsT[c][m], m contiguous in global; zero-pad m>=125 ----
    for (int i = tid; i < C_ * MP; i += 256) {
        const int c = i >> 7;
        const int m = i & 127;
        xsT[c * XS_STRIDE + m] = (m < M_) ? xn[c * (T_ * V_) + m] : 0.f;
    }
    __syncthreads();

    // ---- GEMM1 (f32x2): acc2[p][f] accumulates rows (m0+2p, m0+2p+1) ----
    u64 acc2[4][4];
    #pragma unroll
    for (int p = 0; p < 4; ++p)
        #pragma unroll
        for (int ff = 0; ff < 4; ++ff) acc2[p][ff] = 0ULL;

    #pragma unroll 8
    for (int c = 0; c < C_; ++c) {
        const float4 wv = *(const float4*)&Ws[c * F_ + f0];
        u64 wd[4];
        PACK2(wd[0], wv.x, wv.x);
        PACK2(wd[1], wv.y, wv.y);
        PACK2(wd[2], wv.z, wv.z);
        PACK2(wd[3], wv.w, wv.w);
        const u64* xrow = (const u64*)&xsT[c * XS_STRIDE + m0];  // m0 is 8-aligned
        u64 xp[4] = {xrow[0], xrow[1], xrow[2], xrow[3]};
        #pragma unroll
        for (int p = 0; p < 4; ++p) {
            FMA2(acc2[p][0], xp[p], wd[0], acc2[p][0]);
            FMA2(acc2[p][1], xp[p], wd[1], acc2[p][1]);
            FMA2(acc2[p][2], xp[p], wd[2], acc2[p][2]);
            FMA2(acc2[p][3], xp[p], wd[3], acc2[p][3]);
        }
    }

    // ---- f1/f2 partials (pairwise), unpack, hs store ----
    const float4 a1v = *(const float4*)&a1s[f0];
    const float4 a2v = *(const float4*)&a2s[f0];
    u64 a1d[4], a2d[4];
    PACK2(a1d[0], a1v.x, a1v.x); PACK2(a1d[1], a1v.y, a1v.y);
    PACK2(a1d[2], a1v.z, a1v.z); PACK2(a1d[3], a1v.w, a1v.w);
    PACK2(a2d[0], a2v.x, a2v.x); PACK2(a2d[1], a2v.y, a2v.y);
    PACK2(a2d[2], a2v.z, a2v.z); PACK2(a2d[3], a2v.w, a2v.w);

    u64 s1p[4], s2p[4];
    #pragma unroll
    for (int p = 0; p < 4; ++p) { s1p[p] = 0ULL; s2p[p] = 0ULL; }
    #pragma unroll
    for (int p = 0; p < 4; ++p)
        #pragma unroll
        for (int ff = 0; ff < 4; ++ff) {
            FMA2(s1p[p], acc2[p][ff], a1d[ff], s1p[p]);
            FMA2(s2p[p], acc2[p][ff], a2d[ff], s2p[p]);
        }

    float hv[8][4];
    #pragma unroll
    for (int p = 0; p < 4; ++p)
        #pragma unroll
        for (int ff = 0; ff < 4; ++ff)
            UNPACK2(hv[2 * p][ff], hv[2 * p + 1][ff], acc2[p][ff]);
    #pragma unroll
    for (int k = 0; k < 8; ++k)
        *(float4*)&hs[(m0 + k) * HS_STRIDE + f0] =
            make_float4(hv[k][0], hv[k][1], hv[k][2], hv[k][3]);

    float s1[8], s2[8];
    #pragma unroll
    for (int p = 0; p < 4; ++p) {
        UNPACK2(s1[2 * p], s1[2 * p + 1], s1p[p]);
        UNPACK2(s2[2 * p], s2[2 * p + 1], s2p[p]);
    }
    #pragma unroll
    for (int d = 1; d < 16; d <<= 1) {
        #pragma unroll
        for (int k = 0; k < 8; ++k) {
            s1[k] += __shfl_xor_sync(0xffffffffu, s1[k], d);
            s2[k] += __shfl_xor_sync(0xffffffffu, s2[k], d);
        }
    }
    if (tf == 0) {
        #pragma unroll
        for (int k = 0; k < 8; ++k) { f1s[m0 + k] = s1[k]; f2s[m0 + k] = s2[k]; }
    }
    __syncthreads();

    // ---- masked leaky-relu + row softmax ----
    if (tid < M_) {
        const int m  = tid;
        const int tt = m / V_;
        const int i  = m - tt * V_;
        const int jb = tt * V_;
        const float fi = f1s[m];
        float e[V_];
        float mx = NEG_INF_;
        #pragma unroll
        for (int j = 0; j < V_; ++j) {
            float v = fi + f2s[jb + j];
            v = (v > 0.f) ? v : ALPHA * v;
            v = (adjs[i * V_ + j] > 0) ? v : NEG_INF_;
            e[j] = v;
            mx = fmaxf(mx, v);
        }
        float s = 0.f;
        #pragma unroll
        for (int j = 0; j < V_; ++j) { const float p = __expf(e[j] - mx); e[j] = p; s += p; }
        const float inv = 1.f / s;
        #pragma unroll
        for (int j = 0; j < V_; ++j) attm[m * ATT_STRIDE + j] = e[j] * inv;
    }
    __syncthreads();

    // ---- GEMM2 (scalar, proven round-2 form) ----
    float o[8][4];
    #pragma unroll
    for (int k = 0; k < 8; ++k)
        #pragma unroll
        for (int ff = 0; ff < 4; ++ff) o[k][ff] = 0.f;

    const int baseA = (m0 / V_) * V_;
    int baseB = ((m0 + 7) / V_) * V_;
    if (baseB > 100) baseB = 100;
    const int splitK = baseA + V_;

    #pragma unroll
    for (int jb = 0; jb < ATT_STRIDE; jb += 4) {
        float4 hA[4], hB[4];
        #pragma unroll
        for (int jj = 0; jj < 4; ++jj) {
            hA[jj] = *(const float4*)&hs[(baseA + jb + jj) * HS_STRIDE + f0];
            hB[jj] = *(const float4*)&hs[(baseB + jb + jj) * HS_STRIDE + f0];
        }
        #pragma unroll
        for (int k = 0; k < 8; ++k) {
            const float4 av = *(const float4*)&attm[(m0 + k) * ATT_STRIDE + jb];
            const float4* h = (m0 + k >= splitK) ? hB : hA;
            o[k][0] += av.x * h[0].x + av.y * h[1].x + av.z * h[2].x + av.w * h[3].x;
            o[k][1] += av.x * h[0].y + av.y * h[1].y + av.z * h[2].y + av.w * h[3].y;
            o[k][2] += av.x * h[0].z + av.y * h[1].z + av.z * h[2].z + av.w * h[3].z;
            o[k][3] += av.x * h[0].w + av.y * h[1].w + av.z * h[2].w + av.w * h[3].w;
        }
    }

    // ---- ELU + stage transposed (stride 67, scalar stores) ----
    float* os = xsT;
    __syncthreads();
    #pragma unroll
    for (int k = 0; k < 8; ++k) {
        const int m = m0 + k;
        if (m < M_) {
            #pragma unroll
            for (int ff = 0; ff < 4; ++ff) {
                float v = o[k][ff];
                v = (v > 0.f) ? v : expm1f(v);
                os[m * OS_STRIDE + f0 + ff] = v;
            }
        }
    }
    __syncthreads();

    // ---- store out[n][f][t0*25 + m], 125 contiguous per f ----
    for (int idx = tid; idx < F_ * M_; idx += 256) {
        const int f = idx / M_;
        const int m = idx - f * M_;
        outn[f * (T_ * V_) + m] = os[m * OS_STRIDE + f];
    }
}

extern "C" void kernel_launch(void* const* d_in, const int* in_sizes, int n_in,
                              void* d_out, int out_size)
{
    const float* x   = (const float*)d_in[0];
    const int*   adj = (const int*)  d_in[1];
    const float* W   = (const float*)d_in[2];
    const float* a   = (const float*)d_in[3];
    float* out = (float*)d_out;

    cudaFuncSetAttribute(gat_kernel, cudaFuncAttributeMaxDynamicSharedMemorySize, SMEM_BYTES);
    dim3 grid(N_ * (T_ / TPB));
    gat_kernel<<<grid, 256, SMEM_BYTES>>>(x, adj, W, a, out);
}

// round 8
// speedup vs baseline: 1.2031x; 1.0166x over previous
#include <cuda_runtime.h>
#include <cstdint>

#define N_ 64
#define C_ 64
#define T_ 300
#define V_ 25
#define F_ 64
#define TPB 5
#define M_ 125
#define MP 128
#define TV (T_ * V_)
#define XS_ST 68
#define WT_ST 68
#define HS_STRIDE 68
#define ATT_STRIDE 28
#define OS_STRIDE 67
#define ALPHA 0.2f
#define NEG_INF_ -9.0e15f

// ---- smem float offsets ----
#define OFF_XS  0                         // xs[m][c] 128x68 = 8704  (union: out staging)
#define OFF_WT  8704                      // WsT[f][c] 64x68 = 4352
#define OFF_HS  13056                     // hs[m][f] 128x68 = 8704
#define OFF_ATT 21760                     // attm[m][28] = 3584
#define OFF_F2  25344                     // 128
#define OFF_A1  25472                     // 64
#define OFF_A2  25536                     // 64
#define OFF_ADJ 25600                     // 625 ints
#define SMEM_FLOATS 26225
#define SMEM_BYTES (SMEM_FLOATS * 4)      // 104900 B -> 2 CTAs/SM

__device__ __forceinline__ void split_tf32(float v, uint32_t& hi, uint32_t& lo) {
    uint32_t u = __float_as_uint(v) & 0xFFFFE000u;   // exact tf32 (10-bit mantissa)
    hi = u;
    lo = __float_as_uint(v - __uint_as_float(u));    // HW truncates to tf32; err ~2^-22
}

#define MMA_TF32(d, a, b0, b1) \
    asm volatile("mma.sync.aligned.m16n8k8.row.col.f32.tf32.tf32.f32 " \
        "{%0,%1,%2,%3}, {%4,%5,%6,%7}, {%8,%9}, {%0,%1,%2,%3};" \
        : "+f"((d)[0]), "+f"((d)[1]), "+f"((d)[2]), "+f"((d)[3]) \
        : "r"((a)[0]), "r"((a)[1]), "r"((a)[2]), "r"((a)[3]), "r"(b0), "r"(b1))

__global__ void __launch_bounds__(256, 2) gat_kernel(
    const float* __restrict__ x,    // (N, C, T, V)
    const int*   __restrict__ adj,  // (V, V)
    const float* __restrict__ W,    // (C, F)
    const float* __restrict__ a,    // (2F, 1)
    float*       __restrict__ out)  // (N, F, T, V)
{
    extern __shared__ float sm[];
    float* xs   = sm + OFF_XS;
    float* WsT  = sm + OFF_WT;
    float* hs   = sm + OFF_HS;
    float* attm = sm + OFF_ATT;
    float* f2s  = sm + OFF_F2;
    float* a1s  = sm + OFF_A1;
    float* a2s  = sm + OFF_A2;
    int*   adjs = (int*)(sm + OFF_ADJ);
    float* os   = xs;                // out staging reuses xs (dead after MMA phase)

    const int tid = threadIdx.x;
    const int w   = tid >> 5;        // warp 0..7
    const int l   = tid & 31;
    const int g   = l >> 2;          // group 0..7
    const int qt  = l & 3;           // thread-in-group 0..3
    const int tf  = tid & 15;        // GEMM2: f0 = 4*tf
    const int tm  = tid >> 4;        // GEMM2: m0 = 8*tm
    const int f0  = tf << 2;
    const int m0  = tm << 3;

    const int n  = blockIdx.x / (T_ / TPB);
    const int bt = blockIdx.x % (T_ / TPB);
    const int t0 = bt * TPB;
    const float* xn   = x   + (size_t)n * C_ * TV + (size_t)t0 * V_;
    float*       outn = out + (size_t)n * F_ * TV + (size_t)t0 * V_;

    // ---- stage: xs[m][c] (coalesced in m), WsT[f][c], adj, a1/a2, zero attm ----
    for (int i = tid; i < MP * C_; i += 256) {
        const int c = i >> 7;
        const int m = i & 127;
        xs[m * XS_ST + c] = (m < M_) ? xn[c * TV + m] : 0.f;
    }
    for (int i = tid; i < C_ * F_; i += 256) {
        const int c = i >> 6;
        const int f = i & 63;
        WsT[f * WT_ST + c] = W[i];
    }
    for (int i = tid; i < V_ * V_; i += 256) adjs[i] = adj[i];
    if (tid < F_) { a1s[tid] = a[tid]; a2s[tid] = a[F_ + tid]; }
    for (int i = tid; i < MP * ATT_STRIDE; i += 256) attm[i] = 0.f;
    __syncthreads();

    // ---- GEMM1 on tensor pipe: hs[128][64] = xs[128][64] @ WsT^T, tf32 3-term split ----
    {
        float D[8][4];
        #pragma unroll
        for (int nt = 0; nt < 8; ++nt)
            #pragma unroll
            for (int q = 0; q < 4; ++q) D[nt][q] = 0.f;

        const int rA  = (16 * w + g) * XS_ST;
        const int rA8 = rA + 8 * XS_ST;

        #pragma unroll
        for (int ks = 0; ks < 8; ++ks) {
            const int kc = ks * 8 + qt;
            uint32_t ah[4], al[4];
            split_tf32(xs[rA  + kc],     ah[0], al[0]);   // A[g   ][t]
            split_tf32(xs[rA8 + kc],     ah[1], al[1]);   // A[g+8 ][t]
            split_tf32(xs[rA  + kc + 4], ah[2], al[2]);   // A[g   ][t+4]
            split_tf32(xs[rA8 + kc + 4], ah[3], al[3]);   // A[g+8 ][t+4]
            #pragma unroll
            for (int nt = 0; nt < 8; ++nt) {
                uint32_t bh0, bl0, bh1, bl1;
                split_tf32(WsT[(nt * 8 + g) * WT_ST + kc],     bh0, bl0);  // B[t  ][n]
                split_tf32(WsT[(nt * 8 + g) * WT_ST + kc + 4], bh1, bl1);  // B[t+4][n]
                MMA_TF32(D[nt], ah, bh0, bh1);
                MMA_TF32(D[nt], ah, bl0, bl1);
                MMA_TF32(D[nt], al, bh0, bh1);
            }
        }

        // D -> hs: c0,c1 = D[g][2t,2t+1]; c2,c3 = D[g+8][2t,2t+1]
        #pragma unroll
        for (int nt = 0; nt < 8; ++nt) {
            const int cc = nt * 8 + 2 * qt;
            *(float2*)&hs[(16 * w + g)     * HS_STRIDE + cc] = make_float2(D[nt][0], D[nt][1]);
            *(float2*)&hs[(16 * w + 8 + g) * HS_STRIDE + cc] = make_float2(D[nt][2], D[nt][3]);
        }
    }
    __syncthreads();

    // ---- f1/f2 per row (thread tid == row; f1 stays in register for softmax) ----
    float f1 = 0.f;
    if (tid < MP) {
        float f2 = 0.f;
        const float* hr = &hs[tid * HS_STRIDE];
        #pragma unroll
        for (int i = 0; i < 16; ++i) {
            const float4 hv = *(const float4*)&hr[4 * i];
            const float4 a1v = *(const float4*)&a1s[4 * i];
            const float4 a2v = *(const float4*)&a2s[4 * i];
            f1 += hv.x * a1v.x + hv.y * a1v.y + hv.z * a1v.z + hv.w * a1v.w;
            f2 += hv.x * a2v.x + hv.y * a2v.y + hv.z * a2v.z + hv.w * a2v.w;
        }
        f2s[tid] = f2;
    }
    __syncthreads();

    // ---- masked leaky-relu + row softmax ----
    if (tid < M_) {
        const int m = tid;
        const int gg = m / V_;
        const int i  = m - gg * V_;
        const int base = gg * V_;
        float e[V_];
        float mx = NEG_INF_;
        #pragma unroll
        for (int j = 0; j < V_; ++j) {
            float v = f1 + f2s[base + j];
            v = (v > 0.f) ? v : ALPHA * v;
            v = (adjs[i * V_ + j] > 0) ? v : NEG_INF_;
            e[j] = v;
            mx = fmaxf(mx, v);
        }
        float s = 0.f;
        #pragma unroll
        for (int j = 0; j < V_; ++j) { const float p = __expf(e[j] - mx); e[j] = p; s += p; }
        const float inv = 1.f / s;
        #pragma unroll
        for (int j = 0; j < V_; ++j) attm[m * ATT_STRIDE + j] = e[j] * inv;
    }
    __syncthreads();

    // ---- GEMM2 (SIMT, R2/R6-proven): o[m][f] = sum_j att[m][j] * hs[group_j][f] ----
    float o[8][4];
    #pragma unroll
    for (int k = 0; k < 8; ++k)
        #pragma unroll
        for (int ff = 0; ff < 4; ++ff) o[k][ff] = 0.f;

    const int baseA = (m0 / V_) * V_;
    int baseB = ((m0 + 7) / V_) * V_;
    if (baseB > 100) baseB = 100;
    const int splitK = baseA + V_;

    #pragma unroll
    for (int jb = 0; jb < ATT_STRIDE; jb += 4) {
        float4 hA[4], hB[4];
        #pragma unroll
        for (int jj = 0; jj < 4; ++jj) {
            hA[jj] = *(const float4*)&hs[(baseA + jb + jj) * HS_STRIDE + f0];
            hB[jj] = *(const float4*)&hs[(baseB + jb + jj) * HS_STRIDE + f0];
        }
        #pragma unroll
        for (int k = 0; k < 8; ++k) {
            const float4 av = *(const float4*)&attm[(m0 + k) * ATT_STRIDE + jb];
            const float4* h = (m0 + k >= splitK) ? hB : hA;
            o[k][0] += av.x * h[0].x + av.y * h[1].x + av.z * h[2].x + av.w * h[3].x;
            o[k][1] += av.x * h[0].y + av.y * h[1].y + av.z * h[2].y + av.w * h[3].y;
            o[k][2] += av.x * h[0].z + av.y * h[1].z + av.z * h[2].z + av.w * h[3].z;
            o[k][3] += av.x * h[0].w + av.y * h[1].w + av.z * h[2].w + av.w * h[3].w;
        }
    }

    // ---- ELU + stage transposed into xs region (dead since MMA; disjoint from hs/attm) ----
    #pragma unroll
    for (int k = 0; k < 8; ++k) {
        const int m = m0 + k;
        if (m < M_) {
            #pragma unroll
            for (int ff = 0; ff < 4; ++ff) {
                float v = o[k][ff];
                v = (v > 0.f) ? v : expm1f(v);
                os[m * OS_STRIDE + f0 + ff] = v;
            }
        }
    }
    __syncthreads();

    // ---- store: out[n][f][t0*25 + m], 125 contiguous floats per f ----
    for (int f = w; f < F_; f += 8) {
        for (int mm = l; mm < M_; mm += 32)
            outn[f * TV + mm] = os[mm * OS_STRIDE + f];
    }
}

extern "C" void kernel_launch(void* const* d_in, const int* in_sizes, int n_in,
                              void* d_out, int out_size)
{
    const float* x   = (const float*)d_in[0];
    const int*   adj = (const int*)  d_in[1];
    const float* W   = (const float*)d_in[2];
    const float* a   = (const float*)d_in[3];
    float* out = (float*)d_out;

    cudaFuncSetAttribute(gat_kernel, cudaFuncAttributeMaxDynamicSharedMemorySize, SMEM_BYTES);
    dim3 grid(N_ * (T_ / TPB));
    gat_kernel<<<grid, 256, SMEM_BYTES>>>(x, adj, W, a, out);
}